// round 2
// baseline (speedup 1.0000x reference)
#include <cuda_runtime.h>
#include <cstdint>

#define NN  100000
#define NE  1600000
#define NG  512
#define LL  1000
#define FXD 4
#define FXT 5
#define H   64
#define H2  128
#define NOUT 2

// ---------------- scratch (device globals; no allocation allowed) ----------------
__device__ float  d_deg[NN];
__device__ float  d_dis[NN];
__device__ int    d_er[NE];
__device__ int    d_ec[NE];
__device__ float  d_ew[NE];
__device__ float4 d_aggx[NN];          // [N,4] aggregated raw x
__device__ float4 d_h1[NN * (H/4)];    // [N,64] relu layer-1 output
__device__ float4 d_aggh[NN * (H/4)];  // [N,64] aggregated h1
__device__ int    d_gbits[NG * H2];    // pooled max(h2) as ordered int bits
__device__ float  d_tmax[NG * H];      // conv1d branch pooled output

__device__ __forceinline__ void red_add4(float4* p, float4 v) {
    unsigned long long gp = (unsigned long long)__cvta_generic_to_global(p);
    asm volatile("red.global.add.v4.f32 [%0], {%1,%2,%3,%4};"
                 :: "l"(gp), "f"(v.x), "f"(v.y), "f"(v.z), "f"(v.w) : "memory");
}

// ---------------- K0: init scratch ----------------
__global__ void k_init() {
    int stride = gridDim.x * blockDim.x;
    int tid = blockIdx.x * blockDim.x + threadIdx.x;
    float4 z4 = make_float4(0.f, 0.f, 0.f, 0.f);
    for (int i = tid; i < NN * (H/4); i += stride) d_aggh[i] = z4;
    for (int i = tid; i < NN; i += stride) { d_aggx[i] = z4; d_deg[i] = 1.0f; } // self-loop deg
    for (int i = tid; i < NG * H2; i += stride) d_gbits[i] = 0;                 // relu>=0
}

// ---------------- K1: degree (in-degree over col, self-loop preseeded) ----------------
__global__ void k_deg(const int* __restrict__ ei) {
    int e = blockIdx.x * blockDim.x + threadIdx.x;
    if (e < NE) atomicAdd(&d_deg[ei[NE + e]], 1.0f);
}

// ---------------- K2: dis = rsqrt(deg) ----------------
__global__ void k_dis() {
    int i = blockIdx.x * blockDim.x + threadIdx.x;
    if (i < NN) d_dis[i] = rsqrtf(d_deg[i]);
}

// ---------------- K3: edge prep (norm) + layer-1 raw-x scatter ----------------
__global__ void k_prep(const int* __restrict__ ei, const float* __restrict__ x) {
    int e = blockIdx.x * blockDim.x + threadIdx.x;
    if (e >= NE) return;
    int r = ei[e];
    int c = ei[NE + e];
    float w = d_dis[r] * d_dis[c];
    d_er[e] = r; d_ec[e] = c; d_ew[e] = w;
    float4 xv = ((const float4*)x)[r];
    xv.x *= w; xv.y *= w; xv.z *= w; xv.w *= w;
    red_add4(&d_aggx[c], xv);
}

// ---------------- K4: h1 = relu((aggx + dis^2 * x) @ W1 + b1) ----------------
__global__ void k_h1(const float* __restrict__ x,
                     const float* __restrict__ W1, const float* __restrict__ b1) {
    int gid = blockIdx.x * blockDim.x + threadIdx.x;  // N*64 threads
    if (gid >= NN * H) return;
    int i = gid >> 6;
    int f = gid & 63;
    float4 a = d_aggx[i];
    float4 xv = ((const float4*)x)[i];
    float s = d_dis[i] * d_dis[i];
    a.x += s * xv.x; a.y += s * xv.y; a.z += s * xv.z; a.w += s * xv.w;
    float h = b1[f] + a.x * W1[f] + a.y * W1[H + f] + a.z * W1[2*H + f] + a.w * W1[3*H + f];
    ((float*)d_h1)[gid] = fmaxf(h, 0.f);
}

// ---------------- K5: layer-2 scatter: aggh[c] += w * h1[r]  (16 threads/edge, float4) ----------------
__global__ void k_scatter() {
    int gid = blockIdx.x * blockDim.x + threadIdx.x;  // NE*16 threads
    if (gid >= NE * 16) return;
    int e  = gid >> 4;
    int ch = gid & 15;
    int r = d_er[e];
    int c = d_ec[e];
    float w = d_ew[e];
    float4 v = d_h1[r * 16 + ch];
    v.x *= w; v.y *= w; v.z *= w; v.w *= w;
    red_add4(&d_aggh[c * 16 + ch], v);
}

// ---------------- K6: h2 = relu((aggh + dis^2*h1) @ W2 + b2), fused max-pool by graph ----------------
__global__ void k_h2pool(const float* __restrict__ W2, const float* __restrict__ b2,
                         const int* __restrict__ batch) {
    __shared__ float v[4][H];
    int i0 = blockIdx.x * 4;                // 25000 blocks * 4 nodes
    int tid = threadIdx.x;                  // 128 threads
    for (int idx = tid; idx < 4 * H; idx += 128) {
        int n = idx >> 6, f = idx & 63;
        int i = i0 + n;
        float s = d_dis[i] * d_dis[i];
        v[n][f] = ((const float*)d_aggh)[i * H + f] + s * ((const float*)d_h1)[i * H + f];
    }
    __syncthreads();
    int f = tid;  // output feature 0..127
    float a0 = b2[f], a1 = a0, a2 = a0, a3 = a0;
#pragma unroll
    for (int k = 0; k < H; k++) {
        float wv = W2[k * H2 + f];
        a0 += v[0][k] * wv;
        a1 += v[1][k] * wv;
        a2 += v[2][k] * wv;
        a3 += v[3][k] * wv;
    }
    int b0 = batch[i0 + 0], b1i = batch[i0 + 1];
    int b2i = batch[i0 + 2], b3 = batch[i0 + 3];
    atomicMax(&d_gbits[b0  * H2 + f], __float_as_int(fmaxf(a0, 0.f)));
    atomicMax(&d_gbits[b1i * H2 + f], __float_as_int(fmaxf(a1, 0.f)));
    atomicMax(&d_gbits[b2i * H2 + f], __float_as_int(fmaxf(a2, 0.f)));
    atomicMax(&d_gbits[b3  * H2 + f], __float_as_int(fmaxf(a3, 0.f)));
}

// ---------------- K7: conv1d branch: t = max_l relu(conv1d(target^T)) ----------------
__global__ void k_conv1d(const float* __restrict__ target,
                         const float* __restrict__ Wc, const float* __restrict__ bc) {
    __shared__ float sh[LL * FXT];          // 20 KB: one graph's target [L,FXT]
    __shared__ float red[256];
    int g = blockIdx.x;
    int tid = threadIdx.x;                  // 256 threads
    const float* tg = target + (size_t)g * LL * FXT;
    for (int idx = tid; idx < LL * FXT; idx += 256) sh[idx] = tg[idx];
    __syncthreads();

    int c   = tid & 63;                     // output channel
    int seg = tid >> 6;                     // 0..3 segment of L
    float w[FXT][3];
#pragma unroll
    for (int i = 0; i < FXT; i++)
#pragma unroll
        for (int k = 0; k < 3; k++) w[i][k] = Wc[c * (FXT * 3) + i * 3 + k];

    int start = seg * 250;
    int end = (seg == 3) ? (LL - 2) : (start + 250);   // out positions 0..997
    float m = -3.4e38f;
    for (int l = start; l < end; l++) {
        float s = 0.f;
#pragma unroll
        for (int k = 0; k < 3; k++) {
            const float* row = &sh[(l + k) * FXT];
#pragma unroll
            for (int i = 0; i < FXT; i++) s += row[i] * w[i][k];
        }
        m = fmaxf(m, s);
    }
    red[tid] = m;
    __syncthreads();
    if (seg == 0) {
        m = fmaxf(fmaxf(red[c], red[64 + c]), fmaxf(red[128 + c], red[192 + c]));
        m += bc[c];
        d_tmax[g * H + c] = fmaxf(m, 0.f);   // relu(max) == max(relu)
    }
}

// ---------------- K8: fused final MLPs ----------------
__global__ void k_final(const float* __restrict__ Wg, const float* __restrict__ bg,
                        const float* __restrict__ Wt, const float* __restrict__ bt,
                        const float* __restrict__ Wf, const float* __restrict__ bf,
                        const float* __restrict__ Wo, const float* __restrict__ bo,
                        float* __restrict__ out) {
    __shared__ float sg[H2], st[H], sxc[H2], sy[H];
    int g = blockIdx.x;
    int f = threadIdx.x;                    // 64 threads
    sg[f]      = __int_as_float(d_gbits[g * H2 + f]);
    sg[H + f]  = __int_as_float(d_gbits[g * H2 + H + f]);
    st[f]      = d_tmax[g * H + f];
    __syncthreads();

    float gg = bg[f];
#pragma unroll 8
    for (int j = 0; j < H2; j++) gg += sg[j] * Wg[j * H + f];
    float tt = bt[f];
#pragma unroll 8
    for (int j = 0; j < H; j++) tt += st[j] * Wt[j * H + f];
    sxc[f] = gg;
    sxc[H + f] = tt;
    __syncthreads();

    float y = bf[f];
#pragma unroll 8
    for (int j = 0; j < H2; j++) y += sxc[j] * Wf[j * H + f];
    sy[f] = fmaxf(y, 0.f);
    __syncthreads();

    if (f < NOUT) {
        float o = bo[f];
#pragma unroll 8
        for (int j = 0; j < H; j++) o += sy[j] * Wo[j * NOUT + f];
        out[g * NOUT + f] = o;
    }
}

// ---------------- launch ----------------
extern "C" void kernel_launch(void* const* d_in, const int* in_sizes, int n_in,
                              void* d_out, int out_size) {
    const float* x      = (const float*)d_in[0];
    const int*   ei     = (const int*)d_in[1];      // int32: JAX x64 disabled
    const int*   batch  = (const int*)d_in[2];      // int32
    const float* target = (const float*)d_in[3];
    const float* W1 = (const float*)d_in[4];
    const float* b1 = (const float*)d_in[5];
    const float* W2 = (const float*)d_in[6];
    const float* b2 = (const float*)d_in[7];
    const float* Wg = (const float*)d_in[8];
    const float* bg = (const float*)d_in[9];
    const float* Wc = (const float*)d_in[10];
    const float* bc = (const float*)d_in[11];
    const float* Wt = (const float*)d_in[12];
    const float* bt = (const float*)d_in[13];
    const float* Wf = (const float*)d_in[14];
    const float* bf = (const float*)d_in[15];
    const float* Wo = (const float*)d_in[16];
    const float* bo = (const float*)d_in[17];
    float* out = (float*)d_out;

    k_init<<<4096, 256>>>();
    k_deg<<<(NE + 255) / 256, 256>>>(ei);
    k_dis<<<(NN + 255) / 256, 256>>>();
    k_prep<<<(NE + 255) / 256, 256>>>(ei, x);
    k_h1<<<(NN * H + 255) / 256, 256>>>(x, W1, b1);
    k_scatter<<<(NE * 16 + 255) / 256, 256>>>();
    k_h2pool<<<NN / 4, 128>>>(W2, b2, batch);
    k_conv1d<<<NG, 256>>>(target, Wc, bc);
    k_final<<<NG, 64>>>(Wg, bg, Wt, bt, Wf, bf, Wo, bo, out);
}